// round 2
// baseline (speedup 1.0000x reference)
#include <cuda_runtime.h>
#include <cuda_bf16.h>
#include <cstdint>

// ============================================================================
// GraphConstructionActorHead: score all N*N ordered node pairs with a 3-layer
// MLP (Linear->LN->ReLU x2 -> Linear(1)), masked.
//
// Portable-PTX plan (ptxas here targets sm_103 WITHOUT the 'a' feature set, so
// tcgen05/TMEM are unavailable; mma.sync bf16 + ldmatrix are family-common):
//   k0: A[i] = emb_i @ W1[:64] + b1 ; B[j] = emb_j @ W1[64:]
//   k1: W2^T split to bf16 hi/lo, pre-swizzled [n][k] rows; pack consts
//   main: tile = 128 pairs (one i, 128 consecutive j), 4 warps, warp owns 32 rows:
//     thread r: x = A[i]+B[j]; LN1+ReLU; bf16 hi/lo -> warp-private smem rows
//     warp: ldmatrix A frags; 3-pass mma.sync m16n8k16 bf16 (hh + h*lo + lo*h)
//           W2-hi fragments resident in registers for the entire kernel
//     epilogue on accum fragments: +b2, LN2 (shfl.bfly), ReLU, dot W3, mask
// ============================================================================

#define NN 1024
#define NUM_TILES 8192            // 1024 i * 8 j-blocks
#define GRID_MAIN 304             // 2 CTAs/SM * 152 SMs
#define SMEM_BYTES (49152 + 1024)

// ---------------- device scratch (static allocation — allowed) --------------
__device__ float g_A[NN * 64];
__device__ float g_B[NN * 64];
__device__ __nv_bfloat16 g_w2hi[64 * 64];   // [n][k] rows of 128B, XOR-swizzled
__device__ __nv_bfloat16 g_w2lo[64 * 64];
__device__ float4 g_gb1[32];                // (g1[2t],be1[2t],g1[2t+1],be1[2t+1])
__device__ float4 g_epi[64];                // per col: (g2, be2, W3, b2)

// ---------------- PTX helpers (family-common only) --------------------------
__device__ __forceinline__ uint32_t smem_to_u32(const void* p) {
    uint32_t a;
    asm("{ .reg .u64 t; cvta.to.shared.u64 t, %1; cvt.u32.u64 %0, t; }"
        : "=r"(a) : "l"(p));
    return a;
}
__device__ __forceinline__ void ldm_x4(uint32_t* r, uint32_t addr) {
    asm volatile("ldmatrix.sync.aligned.m8n8.x4.shared.b16 {%0,%1,%2,%3}, [%4];"
                 : "=r"(r[0]), "=r"(r[1]), "=r"(r[2]), "=r"(r[3]) : "r"(addr));
}
__device__ __forceinline__ void ldm_x2(uint32_t& r0, uint32_t& r1, uint32_t addr) {
    asm volatile("ldmatrix.sync.aligned.m8n8.x2.shared.b16 {%0,%1}, [%2];"
                 : "=r"(r0), "=r"(r1) : "r"(addr));
}
__device__ __forceinline__ void mma_bf16(float* c, const uint32_t* a,
                                         uint32_t b0, uint32_t b1) {
    asm volatile(
        "mma.sync.aligned.m16n8k16.row.col.f32.bf16.bf16.f32 "
        "{%0,%1,%2,%3}, {%4,%5,%6,%7}, {%8,%9}, {%0,%1,%2,%3};"
        : "+f"(c[0]), "+f"(c[1]), "+f"(c[2]), "+f"(c[3])
        : "r"(a[0]), "r"(a[1]), "r"(a[2]), "r"(a[3]), "r"(b0), "r"(b1));
}

// swizzled byte offset within a [rows][128B] tile
__device__ __host__ __forceinline__ int swz(int row, int chunk) {
    return row * 128 + ((chunk ^ (row & 7)) << 4);
}

// ---------------- kernel 0: A/B precompute ----------------------------------
__global__ void precompute_ab(const float* __restrict__ emb,
                              const float* __restrict__ W1,
                              const float* __restrict__ b1) {
    __shared__ float e[64];
    int i = blockIdx.x, h = threadIdx.x;
    e[h] = emb[i * 64 + h];
    __syncthreads();
    float a = b1[h], b = 0.f;
#pragma unroll
    for (int d = 0; d < 64; d++) {
        float ed = e[d];
        a = fmaf(ed, W1[d * 64 + h], a);
        b = fmaf(ed, W1[(64 + d) * 64 + h], b);
    }
    g_A[i * 64 + h] = a;
    g_B[i * 64 + h] = b;
}

// ---------------- kernel 1: W2^T bf16 split + packed constants --------------
__global__ void precompute_misc(const float* __restrict__ W2,
                                const float* __restrict__ g1, const float* __restrict__ be1,
                                const float* __restrict__ g2, const float* __restrict__ be2,
                                const float* __restrict__ W3, const float* __restrict__ b2) {
    int t = threadIdx.x;
    for (int idx = t; idx < 4096; idx += 256) {
        int k = idx >> 6, n = idx & 63;
        float v = W2[k * 64 + n];                 // B[n][k] = W2[k][n]
        __nv_bfloat16 hi = __float2bfloat16(v);
        __nv_bfloat16 lo = __float2bfloat16(v - __bfloat162float(hi));
        int byte = swz(n, k >> 3) + (k & 7) * 2;
        g_w2hi[byte >> 1] = hi;
        g_w2lo[byte >> 1] = lo;
    }
    if (t < 32) g_gb1[t] = make_float4(g1[2 * t], be1[2 * t], g1[2 * t + 1], be1[2 * t + 1]);
    if (t < 64) g_epi[t] = make_float4(g2[t], be2[t], W3[t], b2[t]);
}

// ---------------- main fused pair-MLP kernel --------------------------------
__global__ void __launch_bounds__(128, 2) pair_mlp_kernel(
    const float* __restrict__ mask, const float* __restrict__ b3p,
    float* __restrict__ out) {
    extern __shared__ char smem_raw[];
    uint32_t smem_u = smem_to_u32(smem_raw);
    uint32_t base = (smem_u + 1023) & ~1023u;   // 1024-align so row swizzle is clean

    const uint32_t OFF_AHI = 0;        // h1 hi tile [128 rows x 128B] 16 KB
    const uint32_t OFF_ALO = 16384;    // h1 lo tile                  16 KB
    const uint32_t OFF_BHI = 32768;    // W2^T hi [64 rows x 128B]     8 KB
    const uint32_t OFF_BLO = 40960;    // W2^T lo                      8 KB

    int tid = threadIdx.x;
    int l = tid & 31;
    int wid = tid >> 5;
    int wb = wid << 5;                 // warp's 32-row slice base

    // copy pre-swizzled W2 tiles into smem
    {
        const uint4* shi = (const uint4*)g_w2hi;
        const uint4* slo = (const uint4*)g_w2lo;
        uint32_t dhi = base + OFF_BHI, dlo = base + OFF_BLO;
#pragma unroll
        for (int t = 0; t < 4; t++) {
            ((uint4*)(size_t)0)[0];  // (never executed path guard removed below)
        }
        // plain copies
        uint4* ph = (uint4*)(smem_raw + (base - smem_u) + OFF_BHI);
        uint4* pl = (uint4*)(smem_raw + (base - smem_u) + OFF_BLO);
#pragma unroll
        for (int t = 0; t < 4; t++) {
            ph[tid + 128 * t] = __ldg(shi + tid + 128 * t);
            pl[tid + 128 * t] = __ldg(slo + tid + 128 * t);
        }
        (void)dhi; (void)dlo;
    }
    __syncthreads();

    // resident W2-hi fragments: bh[kc][nb][2], same for every warp
    uint32_t bh[4][8][2];
    {
        int bl = l & 15;
        int brow_lo = bl & 7;          // row within n8 block
        int bsel = bl >> 3;            // which 16B half of k16
#pragma unroll
        for (int kc = 0; kc < 4; kc++)
#pragma unroll
            for (int nb = 0; nb < 8; nb++) {
                int row = nb * 8 + brow_lo;
                uint32_t addr = base + OFF_BHI + swz(row, kc * 2 + bsel);
                ldm_x2(bh[kc][nb][0], bh[kc][nb][1], addr);
            }
    }
    float b3 = __ldg(b3p);

    char* basep = smem_raw + (base - smem_u);

    for (int T = blockIdx.x; T < NUM_TILES; T += GRID_MAIN) {
        int i = T & 1023;              // j-block-major: CTA reuses B-rows in L1
        int jbase = (T >> 10) << 7;
        int j = jbase + tid;

        // ---- layer 1: x = A[i] + B[j], LN, ReLU, bf16 split -> smem --------
        float x[64];
        {
            const float4* Ar = (const float4*)(g_A + i * 64);
            const float4* Br = (const float4*)(g_B + (size_t)j * 64);
#pragma unroll
            for (int t = 0; t < 16; t++) {
                float4 a = __ldg(Ar + t), b = __ldg(Br + t);
                x[4 * t + 0] = a.x + b.x; x[4 * t + 1] = a.y + b.y;
                x[4 * t + 2] = a.z + b.z; x[4 * t + 3] = a.w + b.w;
            }
        }
        float s0 = 0, s1 = 0, s2 = 0, s3 = 0, q0 = 0, q1 = 0, q2 = 0, q3 = 0;
#pragma unroll
        for (int t = 0; t < 16; t++) {
            s0 += x[4 * t + 0]; s1 += x[4 * t + 1];
            s2 += x[4 * t + 2]; s3 += x[4 * t + 3];
            q0 = fmaf(x[4 * t + 0], x[4 * t + 0], q0);
            q1 = fmaf(x[4 * t + 1], x[4 * t + 1], q1);
            q2 = fmaf(x[4 * t + 2], x[4 * t + 2], q2);
            q3 = fmaf(x[4 * t + 3], x[4 * t + 3], q3);
        }
        float m  = ((s0 + s1) + (s2 + s3)) * (1.f / 64.f);
        float v  = ((q0 + q1) + (q2 + q3)) * (1.f / 64.f) - m * m;
        float rs = rsqrtf(v + 1e-5f);
        float nm = -m * rs;

#pragma unroll
        for (int c = 0; c < 8; c++) {
            float h[8];
#pragma unroll
            for (int u = 0; u < 4; u++) {
                int k = 8 * c + 2 * u;
                float4 gb = __ldg(g_gb1 + (k >> 1));
                float t0 = fmaf(x[k], rs, nm);
                float t1 = fmaf(x[k + 1], rs, nm);
                h[2 * u]     = fmaxf(fmaf(t0, gb.x, gb.y), 0.f);
                h[2 * u + 1] = fmaxf(fmaf(t1, gb.z, gb.w), 0.f);
            }
            uint32_t hiw[4], low[4];
#pragma unroll
            for (int u = 0; u < 4; u++) {
                __nv_bfloat162 hv = __floats2bfloat162_rn(h[2 * u], h[2 * u + 1]);
                float2 hf = __bfloat1622float2(hv);
                __nv_bfloat162 lv =
                    __floats2bfloat162_rn(h[2 * u] - hf.x, h[2 * u + 1] - hf.y);
                hiw[u] = *(uint32_t*)&hv;
                low[u] = *(uint32_t*)&lv;
            }
            int off = swz(tid, c);
            *(uint4*)(basep + OFF_AHI + off) = make_uint4(hiw[0], hiw[1], hiw[2], hiw[3]);
            *(uint4*)(basep + OFF_ALO + off) = make_uint4(low[0], low[1], low[2], low[3]);
        }
        __syncwarp();   // warp-private A slice: rows wb..wb+31 written by this warp only

        // ---- layer 2 GEMM: 3-pass bf16 mma.sync ----------------------------
        // A frag lane addressing (m16n8k16): row = mf*16 + ((l>>3)&1)*8 + (l&7),
        // 16B chunk = kc*2 + (l>>4)
        int arow_lo = ((l >> 3) & 1) * 8 + (l & 7);
        int asel = l >> 4;

        uint32_t ah[2][4][4];
#pragma unroll
        for (int mf = 0; mf < 2; mf++)
#pragma unroll
            for (int kc = 0; kc < 4; kc++) {
                int row = wb + mf * 16 + arow_lo;
                ldm_x4(ah[mf][kc], base + OFF_AHI + swz(row, kc * 2 + asel));
            }

        float acc[2][8][4] = {};

        // pass 1: hi * hi (resident B)
#pragma unroll
        for (int kc = 0; kc < 4; kc++)
#pragma unroll
            for (int nb = 0; nb < 8; nb++) {
                mma_bf16(acc[0][nb], ah[0][kc], bh[kc][nb][0], bh[kc][nb][1]);
                mma_bf16(acc[1][nb], ah[1][kc], bh[kc][nb][0], bh[kc][nb][1]);
            }
        // pass 2: hi_A * lo_B (stream B-lo from smem)
        {
            int bl = l & 15;
            int brow_lo = bl & 7, bsel = bl >> 3;
#pragma unroll
            for (int kc = 0; kc < 4; kc++)
#pragma unroll
                for (int nb = 0; nb < 8; nb++) {
                    uint32_t t0, t1;
                    ldm_x2(t0, t1, base + OFF_BLO + swz(nb * 8 + brow_lo, kc * 2 + bsel));
                    mma_bf16(acc[0][nb], ah[0][kc], t0, t1);
                    mma_bf16(acc[1][nb], ah[1][kc], t0, t1);
                }
        }
        // load A-lo (overwrites ah)
#pragma unroll
        for (int mf = 0; mf < 2; mf++)
#pragma unroll
            for (int kc = 0; kc < 4; kc++) {
                int row = wb + mf * 16 + arow_lo;
                ldm_x4(ah[mf][kc], base + OFF_ALO + swz(row, kc * 2 + asel));
            }
        __syncwarp();   // all lanes done reading A tiles before next overwrite
        // pass 3: lo_A * hi_B (resident B)
#pragma unroll
        for (int kc = 0; kc < 4; kc++)
#pragma unroll
            for (int nb = 0; nb < 8; nb++) {
                mma_bf16(acc[0][nb], ah[0][kc], bh[kc][nb][0], bh[kc][nb][1]);
                mma_bf16(acc[1][nb], ah[1][kc], bh[kc][nb][0], bh[kc][nb][1]);
            }

        // ---- epilogue on fragments: +b2, LN2, ReLU, dot W3, mask -----------
        // acc[mf][nb][{0,1,2,3}] = D[row, col]:
        //   rows: r0 = wb+mf*16+(l>>2), r1 = r0+8 ; cols: nb*8+2c (+1)
        int g = l >> 2, c4 = l & 3;
#pragma unroll
        for (int mf = 0; mf < 2; mf++) {
            float su0 = 0, qu0 = 0, su1 = 0, qu1 = 0;
#pragma unroll
            for (int nb = 0; nb < 8; nb++) {
                float4 e0 = __ldg(g_epi + nb * 8 + 2 * c4);
                float4 e1 = __ldg(g_epi + nb * 8 + 2 * c4 + 1);
                float a0 = acc[mf][nb][0] + e0.w;
                float a1 = acc[mf][nb][1] + e1.w;
                float a2 = acc[mf][nb][2] + e0.w;
                float a3 = acc[mf][nb][3] + e1.w;
                acc[mf][nb][0] = a0; acc[mf][nb][1] = a1;
                acc[mf][nb][2] = a2; acc[mf][nb][3] = a3;
                su0 += a0 + a1; qu0 = fmaf(a0, a0, fmaf(a1, a1, qu0));
                su1 += a2 + a3; qu1 = fmaf(a2, a2, fmaf(a3, a3, qu1));
            }
            su0 += __shfl_xor_sync(0xffffffffu, su0, 1);
            su0 += __shfl_xor_sync(0xffffffffu, su0, 2);
            qu0 += __shfl_xor_sync(0xffffffffu, qu0, 1);
            qu0 += __shfl_xor_sync(0xffffffffu, qu0, 2);
            su1 += __shfl_xor_sync(0xffffffffu, su1, 1);
            su1 += __shfl_xor_sync(0xffffffffu, su1, 2);
            qu1 += __shfl_xor_sync(0xffffffffu, qu1, 1);
            qu1 += __shfl_xor_sync(0xffffffffu, qu1, 2);

            float m0 = su0 * (1.f / 64.f);
            float v0 = qu0 * (1.f / 64.f) - m0 * m0;
            float rs0 = rsqrtf(v0 + 1e-5f), nm0 = -m0 * rs0;
            float m1 = su1 * (1.f / 64.f);
            float v1 = qu1 * (1.f / 64.f) - m1 * m1;
            float rs1 = rsqrtf(v1 + 1e-5f), nm1 = -m1 * rs1;

            float d0 = 0, d1 = 0;
#pragma unroll
            for (int nb = 0; nb < 8; nb++) {
                float4 e0 = __ldg(g_epi + nb * 8 + 2 * c4);
                float4 e1 = __ldg(g_epi + nb * 8 + 2 * c4 + 1);
                float y;
                y = fmaxf(fmaf(fmaf(acc[mf][nb][0], rs0, nm0), e0.x, e0.y), 0.f);
                d0 = fmaf(y, e0.z, d0);
                y = fmaxf(fmaf(fmaf(acc[mf][nb][1], rs0, nm0), e1.x, e1.y), 0.f);
                d0 = fmaf(y, e1.z, d0);
                y = fmaxf(fmaf(fmaf(acc[mf][nb][2], rs1, nm1), e0.x, e0.y), 0.f);
                d1 = fmaf(y, e0.z, d1);
                y = fmaxf(fmaf(fmaf(acc[mf][nb][3], rs1, nm1), e1.x, e1.y), 0.f);
                d1 = fmaf(y, e1.z, d1);
            }
            d0 += __shfl_xor_sync(0xffffffffu, d0, 1);
            d0 += __shfl_xor_sync(0xffffffffu, d0, 2);
            d1 += __shfl_xor_sync(0xffffffffu, d1, 1);
            d1 += __shfl_xor_sync(0xffffffffu, d1, 2);

            if (c4 == 0) {
                int r0 = wb + mf * 16 + g;
                int j0 = jbase + r0, j1 = j0 + 8;
                int p0 = (i << 10) + j0, p1 = (i << 10) + j1;
                float sc0 = (d0 + b3) * __ldg(mask + p0);
                float sc1 = (d1 + b3) * __ldg(mask + p1);
                out[p0] = (j0 == i) ? 0.f : sc0;
                out[p1] = (j1 == i) ? 0.f : sc1;
            }
        }
        __syncwarp();   // lanes rejoin before next tile's STS to the warp slice
    }
}

// ---------------- launch ----------------------------------------------------
extern "C" void kernel_launch(void* const* d_in, const int* in_sizes, int n_in,
                              void* d_out, int out_size) {
    const float* emb  = (const float*)d_in[0];
    const float* mask = (const float*)d_in[1];
    const float* W1   = (const float*)d_in[2];
    const float* b1   = (const float*)d_in[3];
    const float* g1   = (const float*)d_in[4];
    const float* be1  = (const float*)d_in[5];
    const float* W2   = (const float*)d_in[6];
    const float* b2   = (const float*)d_in[7];
    const float* g2   = (const float*)d_in[8];
    const float* be2  = (const float*)d_in[9];
    const float* W3   = (const float*)d_in[10];
    const float* b3   = (const float*)d_in[11];
    float* out = (float*)d_out;

    cudaFuncSetAttribute(pair_mlp_kernel,
                         cudaFuncAttributeMaxDynamicSharedMemorySize, SMEM_BYTES);

    precompute_ab<<<NN, 64>>>(emb, W1, b1);
    precompute_misc<<<1, 256>>>(W2, g1, be1, g2, be2, W3, b2);
    pair_mlp_kernel<<<GRID_MAIN, 128, SMEM_BYTES>>>(mask, b3, out);
}

// round 3
// speedup vs baseline: 1.1093x; 1.1093x over previous
#include <cuda_runtime.h>
#include <cuda_bf16.h>
#include <cstdint>

// ============================================================================
// GraphConstructionActorHead — all N*N pair scores via factored 3-layer MLP.
//   k0: A[i]=emb_i@W1[:64]+b1, B[j]=emb_j@W1[64:], plus per-node stats
//       (sum, sumsq) so LN1 stats need only a per-pair dot.
//   main: tile = 128 pairs (one i, 128 j). Warp owns 32 rows end-to-end.
//     LN1 in regs -> bf16 hi/lo split -> warp-private smem -> ldmatrix ->
//     3-pass bf16 mma.sync (hi*hi + lo*hi + hi*lo, ~2^-16 error) ->
//     epilogue LN2 + W3 dot on fragments (shfl reductions) -> coalesced store.
//   Occupancy: 3 CTAs/SM (regs<=170), grid = one full wave, chunked schedule
//   for L1-resident B blocks.
// ============================================================================

#define NN 1024
#define NUM_TILES 8192
#define GRID_MAIN 456              // 3 CTAs/SM * 152 SMs, single wave
#define SMEM_BYTES 50304

// ---------------- device scratch --------------------------------------------
__device__ float g_A[NN * 64];
__device__ float g_B[NN * 64];
__device__ float2 g_stA[NN];                // (sum, sumsq) of A row
__device__ float2 g_stB[NN];
__device__ __nv_bfloat16 g_w2hi[64 * 64];   // [n][k] rows of 128B, XOR-swizzled
__device__ __nv_bfloat16 g_w2lo[64 * 64];
__device__ float4 g_gb1[32];                // (g1[2t],be1[2t],g1[2t+1],be1[2t+1])
__device__ float4 g_epi[64];                // per col: (g2, be2, W3, b2)

// ---------------- PTX helpers (family-common only) --------------------------
__device__ __forceinline__ uint32_t smem_to_u32(const void* p) {
    uint32_t a;
    asm("{ .reg .u64 t; cvta.to.shared.u64 t, %1; cvt.u32.u64 %0, t; }"
        : "=r"(a) : "l"(p));
    return a;
}
__device__ __forceinline__ void ldm_x4(uint32_t* r, uint32_t addr) {
    asm volatile("ldmatrix.sync.aligned.m8n8.x4.shared.b16 {%0,%1,%2,%3}, [%4];"
                 : "=r"(r[0]), "=r"(r[1]), "=r"(r[2]), "=r"(r[3]) : "r"(addr));
}
__device__ __forceinline__ void ldm_x2(uint32_t& r0, uint32_t& r1, uint32_t addr) {
    asm volatile("ldmatrix.sync.aligned.m8n8.x2.shared.b16 {%0,%1}, [%2];"
                 : "=r"(r0), "=r"(r1) : "r"(addr));
}
__device__ __forceinline__ void mma_bf16(float* c, const uint32_t* a,
                                         uint32_t b0, uint32_t b1) {
    asm volatile(
        "mma.sync.aligned.m16n8k16.row.col.f32.bf16.bf16.f32 "
        "{%0,%1,%2,%3}, {%4,%5,%6,%7}, {%8,%9}, {%0,%1,%2,%3};"
        : "+f"(c[0]), "+f"(c[1]), "+f"(c[2]), "+f"(c[3])
        : "r"(a[0]), "r"(a[1]), "r"(a[2]), "r"(a[3]), "r"(b0), "r"(b1));
}
// swizzled byte offset within a [rows][128B] tile
__device__ __host__ __forceinline__ int swz(int row, int chunk) {
    return row * 128 + ((chunk ^ (row & 7)) << 4);
}

// ---------------- kernel 0: A/B precompute + per-node stats -----------------
__global__ void precompute_ab(const float* __restrict__ emb,
                              const float* __restrict__ W1,
                              const float* __restrict__ b1) {
    __shared__ float e[64];
    __shared__ float part[2][4];
    int i = blockIdx.x, h = threadIdx.x;
    int l = h & 31, w = h >> 5;
    e[h] = emb[i * 64 + h];
    __syncthreads();
    float a0 = b1[h], a1 = 0.f, a2 = 0.f, a3 = 0.f;
    float c0 = 0.f, c1 = 0.f, c2 = 0.f, c3 = 0.f;
#pragma unroll
    for (int d = 0; d < 64; d += 4) {
        float e0 = e[d], e1 = e[d + 1], e2 = e[d + 2], e3 = e[d + 3];
        a0 = fmaf(e0, __ldg(W1 + d * 64 + h), a0);
        a1 = fmaf(e1, __ldg(W1 + (d + 1) * 64 + h), a1);
        a2 = fmaf(e2, __ldg(W1 + (d + 2) * 64 + h), a2);
        a3 = fmaf(e3, __ldg(W1 + (d + 3) * 64 + h), a3);
        c0 = fmaf(e0, __ldg(W1 + (64 + d) * 64 + h), c0);
        c1 = fmaf(e1, __ldg(W1 + (65 + d) * 64 + h), c1);
        c2 = fmaf(e2, __ldg(W1 + (66 + d) * 64 + h), c2);
        c3 = fmaf(e3, __ldg(W1 + (67 + d) * 64 + h), c3);
    }
    float a = (a0 + a1) + (a2 + a3);
    float b = (c0 + c1) + (c2 + c3);
    g_A[i * 64 + h] = a;
    g_B[i * 64 + h] = b;
    float sa = a, qa = a * a, sb = b, qb = b * b;
#pragma unroll
    for (int o = 16; o > 0; o >>= 1) {
        sa += __shfl_xor_sync(0xffffffffu, sa, o);
        qa += __shfl_xor_sync(0xffffffffu, qa, o);
        sb += __shfl_xor_sync(0xffffffffu, sb, o);
        qb += __shfl_xor_sync(0xffffffffu, qb, o);
    }
    if (l == 0) { part[w][0] = sa; part[w][1] = qa; part[w][2] = sb; part[w][3] = qb; }
    __syncthreads();
    if (h == 0) {
        g_stA[i] = make_float2(part[0][0] + part[1][0], part[0][1] + part[1][1]);
        g_stB[i] = make_float2(part[0][2] + part[1][2], part[0][3] + part[1][3]);
    }
}

// ---------------- kernel 1: W2^T bf16 split + packed constants --------------
__global__ void precompute_misc(const float* __restrict__ W2,
                                const float* __restrict__ g1, const float* __restrict__ be1,
                                const float* __restrict__ g2, const float* __restrict__ be2,
                                const float* __restrict__ W3, const float* __restrict__ b2) {
    int idx = blockIdx.x * 256 + threadIdx.x;
    if (idx < 4096) {
        int k = idx >> 6, n = idx & 63;
        float v = W2[k * 64 + n];                 // B[n][k] = W2[k][n]
        __nv_bfloat16 hi = __float2bfloat16(v);
        __nv_bfloat16 lo = __float2bfloat16(v - __bfloat162float(hi));
        int byte = swz(n, k >> 3) + (k & 7) * 2;
        g_w2hi[byte >> 1] = hi;
        g_w2lo[byte >> 1] = lo;
    }
    if (blockIdx.x == 0) {
        int t = threadIdx.x;
        if (t < 32) g_gb1[t] = make_float4(g1[2 * t], be1[2 * t], g1[2 * t + 1], be1[2 * t + 1]);
        if (t < 64) g_epi[t] = make_float4(g2[t], be2[t], W3[t], b2[t]);
    }
}

// ---------------- main fused pair-MLP kernel --------------------------------
__global__ void __launch_bounds__(128, 3) pair_mlp_kernel(
    const float* __restrict__ mask, const float* __restrict__ b3p,
    float* __restrict__ out) {
    extern __shared__ char smem_raw[];
    uint32_t smem_u = smem_to_u32(smem_raw);
    uint32_t base = (smem_u + 1023) & ~1023u;
    char* basep = smem_raw + (base - smem_u);

    const uint32_t OFF_AHI = 0;        // h1 hi [128 rows x 128B] 16 KB
    const uint32_t OFF_ALO = 16384;    // h1 lo                   16 KB
    const uint32_t OFF_BHI = 32768;    // W2^T hi [64 x 128B]      8 KB
    const uint32_t OFF_BLO = 40960;    // W2^T lo                  8 KB

    int tid = threadIdx.x;
    int l = tid & 31;
    int wb = (tid >> 5) << 5;          // warp's 32-row slice base

    // copy pre-swizzled W2 tiles into smem
    {
        uint4* ph = (uint4*)(basep + OFF_BHI);
        uint4* pl = (uint4*)(basep + OFF_BLO);
        const uint4* shi = (const uint4*)g_w2hi;
        const uint4* slo = (const uint4*)g_w2lo;
#pragma unroll
        for (int t = 0; t < 4; t++) {
            ph[tid + 128 * t] = __ldg(shi + tid + 128 * t);
            pl[tid + 128 * t] = __ldg(slo + tid + 128 * t);
        }
    }
    __syncthreads();

    // resident W2-hi fragments (identical for all warps): bh[kc][nb][2]
    int bl = l & 15;
    int brow_lo = bl & 7, bsel = bl >> 3;
    uint32_t bh[4][8][2];
#pragma unroll
    for (int kc = 0; kc < 4; kc++)
#pragma unroll
        for (int nb = 0; nb < 8; nb++)
            ldm_x2(bh[kc][nb][0], bh[kc][nb][1],
                   base + OFF_BHI + swz(nb * 8 + brow_lo, kc * 2 + bsel));

    float b3 = __ldg(b3p);
    int arow_lo = ((l >> 3) & 1) * 8 + (l & 7);
    int asel = l >> 4;

    // chunked schedule: consecutive tiles share jbase -> B block L1-resident
    int t0 = (int)(((long long)blockIdx.x * NUM_TILES) / GRID_MAIN);
    int t1 = (int)(((long long)(blockIdx.x + 1) * NUM_TILES) / GRID_MAIN);

    for (int T = t0; T < t1; T++) {
        int i = T & 1023;
        int jbase = (T >> 10) << 7;
        int j = jbase + tid;

        // ---- layer 1: x = A[i]+B[j]; LN via precomputed stats + dot --------
        float x[64];
        float d0 = 0, d1 = 0, d2 = 0, d3 = 0;
        {
            const float4* Ar = (const float4*)(g_A + i * 64);
            const float4* Br = (const float4*)(g_B + (size_t)j * 64);
#pragma unroll
            for (int t = 0; t < 16; t++) {
                float4 a = __ldg(Ar + t), b = __ldg(Br + t);
                x[4 * t + 0] = a.x + b.x; x[4 * t + 1] = a.y + b.y;
                x[4 * t + 2] = a.z + b.z; x[4 * t + 3] = a.w + b.w;
                d0 = fmaf(a.x, b.x, d0); d1 = fmaf(a.y, b.y, d1);
                d2 = fmaf(a.z, b.z, d2); d3 = fmaf(a.w, b.w, d3);
            }
        }
        float2 stA = __ldg(g_stA + i);
        float2 stB = __ldg(g_stB + j);
        float dot = (d0 + d1) + (d2 + d3);
        float m  = (stA.x + stB.x) * (1.f / 64.f);
        float v  = (stA.y + stB.y + 2.f * dot) * (1.f / 64.f) - m * m;
        float rs = rsqrtf(v + 1e-5f);
        float nm = -m * rs;

#pragma unroll
        for (int c = 0; c < 8; c++) {
            float h[8];
#pragma unroll
            for (int u = 0; u < 4; u++) {
                int k = 8 * c + 2 * u;
                float4 gb = __ldg(g_gb1 + (k >> 1));
                float u0 = fmaf(x[k], rs, nm);
                float u1 = fmaf(x[k + 1], rs, nm);
                h[2 * u]     = fmaxf(fmaf(u0, gb.x, gb.y), 0.f);
                h[2 * u + 1] = fmaxf(fmaf(u1, gb.z, gb.w), 0.f);
            }
            uint32_t hiw[4], low[4];
#pragma unroll
            for (int u = 0; u < 4; u++) {
                __nv_bfloat162 hv = __floats2bfloat162_rn(h[2 * u], h[2 * u + 1]);
                float2 hf = __bfloat1622float2(hv);
                __nv_bfloat162 lv =
                    __floats2bfloat162_rn(h[2 * u] - hf.x, h[2 * u + 1] - hf.y);
                hiw[u] = *(uint32_t*)&hv;
                low[u] = *(uint32_t*)&lv;
            }
            int off = swz(tid, c);
            *(uint4*)(basep + OFF_AHI + off) = make_uint4(hiw[0], hiw[1], hiw[2], hiw[3]);
            *(uint4*)(basep + OFF_ALO + off) = make_uint4(low[0], low[1], low[2], low[3]);
        }
        __syncwarp();

        // ---- layer 2 GEMM: 3-pass bf16, per-kc A streaming -----------------
        float acc[2][8][4] = {};
#pragma unroll
        for (int kc = 0; kc < 4; kc++) {
            uint32_t ahi[2][4], alo[2][4];
            ldm_x4(ahi[0], base + OFF_AHI + swz(wb + arow_lo, kc * 2 + asel));
            ldm_x4(ahi[1], base + OFF_AHI + swz(wb + 16 + arow_lo, kc * 2 + asel));
            ldm_x4(alo[0], base + OFF_ALO + swz(wb + arow_lo, kc * 2 + asel));
            ldm_x4(alo[1], base + OFF_ALO + swz(wb + 16 + arow_lo, kc * 2 + asel));
#pragma unroll
            for (int nb = 0; nb < 8; nb++) {
                uint32_t t0r, t1r;
                ldm_x2(t0r, t1r, base + OFF_BLO + swz(nb * 8 + brow_lo, kc * 2 + bsel));
                mma_bf16(acc[0][nb], ahi[0], bh[kc][nb][0], bh[kc][nb][1]);
                mma_bf16(acc[1][nb], ahi[1], bh[kc][nb][0], bh[kc][nb][1]);
                mma_bf16(acc[0][nb], alo[0], bh[kc][nb][0], bh[kc][nb][1]);
                mma_bf16(acc[1][nb], alo[1], bh[kc][nb][0], bh[kc][nb][1]);
                mma_bf16(acc[0][nb], ahi[0], t0r, t1r);
                mma_bf16(acc[1][nb], ahi[1], t0r, t1r);
            }
        }

        // ---- epilogue: +b2, LN2 (shfl), ReLU, dot W3 -----------------------
        int c4 = l & 3;
        float dd[4];
#pragma unroll
        for (int mf = 0; mf < 2; mf++) {
            float su0 = 0, qu0 = 0, su1 = 0, qu1 = 0;
#pragma unroll
            for (int nb = 0; nb < 8; nb++) {
                float4 e0 = __ldg(g_epi + nb * 8 + 2 * c4);
                float4 e1 = __ldg(g_epi + nb * 8 + 2 * c4 + 1);
                float a0 = acc[mf][nb][0] + e0.w;
                float a1 = acc[mf][nb][1] + e1.w;
                float a2 = acc[mf][nb][2] + e0.w;
                float a3 = acc[mf][nb][3] + e1.w;
                acc[mf][nb][0] = a0; acc[mf][nb][1] = a1;
                acc[mf][nb][2] = a2; acc[mf][nb][3] = a3;
                su0 += a0 + a1; qu0 = fmaf(a0, a0, fmaf(a1, a1, qu0));
                su1 += a2 + a3; qu1 = fmaf(a2, a2, fmaf(a3, a3, qu1));
            }
            su0 += __shfl_xor_sync(0xffffffffu, su0, 1);
            su0 += __shfl_xor_sync(0xffffffffu, su0, 2);
            qu0 += __shfl_xor_sync(0xffffffffu, qu0, 1);
            qu0 += __shfl_xor_sync(0xffffffffu, qu0, 2);
            su1 += __shfl_xor_sync(0xffffffffu, su1, 1);
            su1 += __shfl_xor_sync(0xffffffffu, su1, 2);
            qu1 += __shfl_xor_sync(0xffffffffu, qu1, 1);
            qu1 += __shfl_xor_sync(0xffffffffu, qu1, 2);

            float m0 = su0 * (1.f / 64.f);
            float v0 = qu0 * (1.f / 64.f) - m0 * m0;
            float rs0 = rsqrtf(v0 + 1e-5f), nm0 = -m0 * rs0;
            float m1 = su1 * (1.f / 64.f);
            float v1 = qu1 * (1.f / 64.f) - m1 * m1;
            float rs1 = rsqrtf(v1 + 1e-5f), nm1 = -m1 * rs1;

            float w0 = 0, w1 = 0;
#pragma unroll
            for (int nb = 0; nb < 8; nb++) {
                float4 e0 = __ldg(g_epi + nb * 8 + 2 * c4);
                float4 e1 = __ldg(g_epi + nb * 8 + 2 * c4 + 1);
                float y;
                y = fmaxf(fmaf(fmaf(acc[mf][nb][0], rs0, nm0), e0.x, e0.y), 0.f);
                w0 = fmaf(y, e0.z, w0);
                y = fmaxf(fmaf(fmaf(acc[mf][nb][1], rs0, nm0), e1.x, e1.y), 0.f);
                w0 = fmaf(y, e1.z, w0);
                y = fmaxf(fmaf(fmaf(acc[mf][nb][2], rs1, nm1), e0.x, e0.y), 0.f);
                w1 = fmaf(y, e0.z, w1);
                y = fmaxf(fmaf(fmaf(acc[mf][nb][3], rs1, nm1), e1.x, e1.y), 0.f);
                w1 = fmaf(y, e1.z, w1);
            }
            w0 += __shfl_xor_sync(0xffffffffu, w0, 1);
            w0 += __shfl_xor_sync(0xffffffffu, w0, 2);
            w1 += __shfl_xor_sync(0xffffffffu, w1, 1);
            w1 += __shfl_xor_sync(0xffffffffu, w1, 2);
            dd[mf * 2 + 0] = w0;
            dd[mf * 2 + 1] = w1;
        }

        // gather so lane l holds row wb+l -> coalesced mask load + store
        int src = (l & 7) * 4;
        float a0 = __shfl_sync(0xffffffffu, dd[0], src);
        float a1 = __shfl_sync(0xffffffffu, dd[1], src);
        float a2 = __shfl_sync(0xffffffffu, dd[2], src);
        float a3 = __shfl_sync(0xffffffffu, dd[3], src);
        float dv = (l < 8) ? a0 : (l < 16) ? a1 : (l < 24) ? a2 : a3;
        int jj = jbase + wb + l;
        int p = (i << 10) + jj;
        float sc = (dv + b3) * __ldg(mask + p);
        out[p] = (jj == i) ? 0.f : sc;

        __syncwarp();   // lanes rejoin before next tile's STS to the warp slice
    }
}

// ---------------- launch ----------------------------------------------------
extern "C" void kernel_launch(void* const* d_in, const int* in_sizes, int n_in,
                              void* d_out, int out_size) {
    const float* emb  = (const float*)d_in[0];
    const float* mask = (const float*)d_in[1];
    const float* W1   = (const float*)d_in[2];
    const float* b1   = (const float*)d_in[3];
    const float* g1   = (const float*)d_in[4];
    const float* be1  = (const float*)d_in[5];
    const float* W2   = (const float*)d_in[6];
    const float* b2   = (const float*)d_in[7];
    const float* g2   = (const float*)d_in[8];
    const float* be2  = (const float*)d_in[9];
    const float* W3   = (const float*)d_in[10];
    const float* b3   = (const float*)d_in[11];
    float* out = (float*)d_out;

    cudaFuncSetAttribute(pair_mlp_kernel,
                         cudaFuncAttributeMaxDynamicSharedMemorySize, SMEM_BYTES);

    precompute_ab<<<NN, 64>>>(emb, W1, b1);
    precompute_misc<<<16, 256>>>(W2, g1, be1, g2, be2, W3, b2);
    pair_mlp_kernel<<<GRID_MAIN, 128, SMEM_BYTES>>>(mask, b3, out);
}

// round 4
// speedup vs baseline: 1.1856x; 1.0688x over previous
#include <cuda_runtime.h>
#include <cuda_fp16.h>
#include <cstdint>

// ============================================================================
// GraphConstructionActorHead — all N*N pair scores via factored 3-layer MLP.
//   pre (1 launch): A[i]=emb_i@W1[:64]+b1, B[j]=emb_j@W1[64:], per-node
//     (sum,sumsq); W2^T -> fp16, swizzled; packed LN/epilogue consts.
//   main: tile = 128 pairs (one i, 128 j). Warp owns 32 rows end-to-end.
//     LN1 in regs -> fp16 hi/lo split -> warp-private smem -> ldmatrix ->
//     2-pass fp16 mma.sync (hiA*hiB + loA*hiB, residual ~2^-12) ->
//     epilogue LN2 + W3 dot on fragments (shfl) -> coalesced store.
//   4 CTAs/SM (regs<=128, smem 41KB), single wave, chunked schedule.
// ============================================================================

#define NN 1024
#define NUM_TILES 8192
#define GRID_MAIN 608              // 4 CTAs/SM * 152 SMs, single wave
#define SMEM_BYTES 41984

// ---------------- device scratch --------------------------------------------
__device__ float g_A[NN * 64];
__device__ float g_B[NN * 64];
__device__ float2 g_stA[NN];                // (sum, sumsq) of A row
__device__ float2 g_stB[NN];
__device__ __half g_w2hi[64 * 64];          // [n][k] rows of 128B, XOR-swizzled
__device__ float4 g_gb1[32];                // (g1[2t],be1[2t],g1[2t+1],be1[2t+1])
__device__ float4 g_epi[64];                // per col: (g2, be2, W3, b2)

// ---------------- PTX helpers (family-common only) --------------------------
__device__ __forceinline__ uint32_t smem_to_u32(const void* p) {
    uint32_t a;
    asm("{ .reg .u64 t; cvta.to.shared.u64 t, %1; cvt.u32.u64 %0, t; }"
        : "=r"(a) : "l"(p));
    return a;
}
__device__ __forceinline__ void ldm_x4(uint32_t* r, uint32_t addr) {
    asm volatile("ldmatrix.sync.aligned.m8n8.x4.shared.b16 {%0,%1,%2,%3}, [%4];"
                 : "=r"(r[0]), "=r"(r[1]), "=r"(r[2]), "=r"(r[3]) : "r"(addr));
}
__device__ __forceinline__ void mma_f16(float* c, const uint32_t* a,
                                        uint32_t b0, uint32_t b1) {
    asm volatile(
        "mma.sync.aligned.m16n8k16.row.col.f32.f16.f16.f32 "
        "{%0,%1,%2,%3}, {%4,%5,%6,%7}, {%8,%9}, {%0,%1,%2,%3};"
        : "+f"(c[0]), "+f"(c[1]), "+f"(c[2]), "+f"(c[3])
        : "r"(a[0]), "r"(a[1]), "r"(a[2]), "r"(a[3]), "r"(b0), "r"(b1));
}
// swizzled byte offset within a [rows][128B] tile
__device__ __host__ __forceinline__ int swz(int row, int chunk) {
    return row * 128 + ((chunk ^ (row & 7)) << 4);
}

// ---------------- merged precompute (1 launch) ------------------------------
// blocks 0..1023: A/B rows + stats; 1024..1087: W2 fp16 swizzle; 1088: consts
__global__ void precompute_all(const float* __restrict__ emb,
                               const float* __restrict__ W1,
                               const float* __restrict__ b1,
                               const float* __restrict__ W2,
                               const float* __restrict__ g1, const float* __restrict__ be1,
                               const float* __restrict__ g2, const float* __restrict__ be2,
                               const float* __restrict__ W3, const float* __restrict__ b2) {
    int bid = blockIdx.x;
    if (bid < NN) {
        __shared__ float e[64];
        __shared__ float part[2][4];
        int i = bid, h = threadIdx.x;
        int l = h & 31, w = h >> 5;
        e[h] = emb[i * 64 + h];
        __syncthreads();
        float a0 = b1[h], a1 = 0.f, a2 = 0.f, a3 = 0.f;
        float c0 = 0.f, c1 = 0.f, c2 = 0.f, c3 = 0.f;
#pragma unroll
        for (int d = 0; d < 64; d += 4) {
            float e0 = e[d], e1 = e[d + 1], e2 = e[d + 2], e3 = e[d + 3];
            a0 = fmaf(e0, __ldg(W1 + d * 64 + h), a0);
            a1 = fmaf(e1, __ldg(W1 + (d + 1) * 64 + h), a1);
            a2 = fmaf(e2, __ldg(W1 + (d + 2) * 64 + h), a2);
            a3 = fmaf(e3, __ldg(W1 + (d + 3) * 64 + h), a3);
            c0 = fmaf(e0, __ldg(W1 + (64 + d) * 64 + h), c0);
            c1 = fmaf(e1, __ldg(W1 + (65 + d) * 64 + h), c1);
            c2 = fmaf(e2, __ldg(W1 + (66 + d) * 64 + h), c2);
            c3 = fmaf(e3, __ldg(W1 + (67 + d) * 64 + h), c3);
        }
        float a = (a0 + a1) + (a2 + a3);
        float b = (c0 + c1) + (c2 + c3);
        g_A[i * 64 + h] = a;
        g_B[i * 64 + h] = b;
        float sa = a, qa = a * a, sb = b, qb = b * b;
#pragma unroll
        for (int o = 16; o > 0; o >>= 1) {
            sa += __shfl_xor_sync(0xffffffffu, sa, o);
            qa += __shfl_xor_sync(0xffffffffu, qa, o);
            sb += __shfl_xor_sync(0xffffffffu, sb, o);
            qb += __shfl_xor_sync(0xffffffffu, qb, o);
        }
        if (l == 0) { part[w][0] = sa; part[w][1] = qa; part[w][2] = sb; part[w][3] = qb; }
        __syncthreads();
        if (h == 0) {
            g_stA[i] = make_float2(part[0][0] + part[1][0], part[0][1] + part[1][1]);
            g_stB[i] = make_float2(part[0][2] + part[1][2], part[0][3] + part[1][3]);
        }
    } else if (bid < NN + 64) {
        int idx = (bid - NN) * 64 + threadIdx.x;   // 0..4095
        int k = idx >> 6, n = idx & 63;
        float v = W2[k * 64 + n];                  // B[n][k] = W2[k][n]
        int byte = swz(n, k >> 3) + (k & 7) * 2;
        g_w2hi[byte >> 1] = __float2half_rn(v);
    } else {
        int t = threadIdx.x;
        if (t < 32) g_gb1[t] = make_float4(g1[2 * t], be1[2 * t], g1[2 * t + 1], be1[2 * t + 1]);
        if (t < 64) g_epi[t] = make_float4(g2[t], be2[t], W3[t], b2[t]);
    }
}

// ---------------- main fused pair-MLP kernel --------------------------------
__global__ void __launch_bounds__(128, 4) pair_mlp_kernel(
    const float* __restrict__ mask, const float* __restrict__ b3p,
    float* __restrict__ out) {
    extern __shared__ char smem_raw[];
    uint32_t smem_u = smem_to_u32(smem_raw);
    uint32_t base = (smem_u + 1023) & ~1023u;
    char* basep = smem_raw + (base - smem_u);

    const uint32_t OFF_AHI = 0;        // h1 hi [128 rows x 128B] 16 KB
    const uint32_t OFF_ALO = 16384;    // h1 lo                   16 KB
    const uint32_t OFF_BHI = 32768;    // W2^T hi fp16 [64 x 128B] 8 KB

    int tid = threadIdx.x;
    int l = tid & 31;
    int wb = (tid >> 5) << 5;          // warp's 32-row slice base

    // copy pre-swizzled W2-hi into smem
    {
        uint4* ph = (uint4*)(basep + OFF_BHI);
        const uint4* shi = (const uint4*)g_w2hi;
#pragma unroll
        for (int t = 0; t < 4; t++) ph[tid + 128 * t] = __ldg(shi + tid + 128 * t);
    }
    __syncthreads();

    float b3 = __ldg(b3p);
    int arow_lo = ((l >> 3) & 1) * 8 + (l & 7);
    int asel = l >> 4;
    // B ldmatrix lane mapping (x4 covers 2 nb blocks):
    int brow = (l & 7);
    int bnb_hi = (l >> 4) & 1;         // which of the 2 nb blocks
    int bchunk = (l >> 3) & 1;         // k16 half

    // chunked schedule: consecutive tiles share jbase -> B block L1-resident
    int t0 = (int)(((long long)blockIdx.x * NUM_TILES) / GRID_MAIN);
    int t1 = (int)(((long long)(blockIdx.x + 1) * NUM_TILES) / GRID_MAIN);

    for (int T = t0; T < t1; T++) {
        int i = T & 1023;
        int jbase = (T >> 10) << 7;
        int j = jbase + tid;

        // ---- layer 1: x = A[i]+B[j]; LN stats via precomputed + dot --------
        float x[64];
        float d0 = 0, d1 = 0, d2 = 0, d3 = 0;
        {
            const float4* Ar = (const float4*)(g_A + i * 64);
            const float4* Br = (const float4*)(g_B + (size_t)j * 64);
#pragma unroll
            for (int t = 0; t < 16; t++) {
                float4 a = __ldg(Ar + t), b = __ldg(Br + t);
                x[4 * t + 0] = a.x + b.x; x[4 * t + 1] = a.y + b.y;
                x[4 * t + 2] = a.z + b.z; x[4 * t + 3] = a.w + b.w;
                d0 = fmaf(a.x, b.x, d0); d1 = fmaf(a.y, b.y, d1);
                d2 = fmaf(a.z, b.z, d2); d3 = fmaf(a.w, b.w, d3);
            }
        }
        float2 stA = __ldg(g_stA + i);
        float2 stB = __ldg(g_stB + j);
        float dot = (d0 + d1) + (d2 + d3);
        float m  = (stA.x + stB.x) * (1.f / 64.f);
        float v  = (stA.y + stB.y + 2.f * dot) * (1.f / 64.f) - m * m;
        float rs = rsqrtf(v + 1e-5f);
        float nm = -m * rs;

        // apply LN1+ReLU, fp16 hi/lo split, write warp-private smem rows
#pragma unroll
        for (int c = 0; c < 8; c++) {
            float h[8];
#pragma unroll
            for (int u = 0; u < 4; u++) {
                int k = 8 * c + 2 * u;
                float4 gb = __ldg(g_gb1 + (k >> 1));
                float u0 = fmaf(x[k], rs, nm);
                float u1 = fmaf(x[k + 1], rs, nm);
                h[2 * u]     = fmaxf(fmaf(u0, gb.x, gb.y), 0.f);
                h[2 * u + 1] = fmaxf(fmaf(u1, gb.z, gb.w), 0.f);
            }
            uint32_t hiw[4], low[4];
#pragma unroll
            for (int u = 0; u < 4; u++) {
                __half2 hv = __floats2half2_rn(h[2 * u], h[2 * u + 1]);
                float2 hf = __half22float2(hv);
                __half2 lv = __floats2half2_rn(h[2 * u] - hf.x, h[2 * u + 1] - hf.y);
                hiw[u] = *(uint32_t*)&hv;
                low[u] = *(uint32_t*)&lv;
            }
            int off = swz(tid, c);
            *(uint4*)(basep + OFF_AHI + off) = make_uint4(hiw[0], hiw[1], hiw[2], hiw[3]);
            *(uint4*)(basep + OFF_ALO + off) = make_uint4(low[0], low[1], low[2], low[3]);
        }
        __syncwarp();   // warp-private rows: only intra-warp visibility needed

        // ---- layer 2 GEMM: 2-pass fp16 (hi*hi + lo*hi) ---------------------
        float acc[2][8][4] = {};
#pragma unroll
        for (int kc = 0; kc < 4; kc++) {
            uint32_t ahi0[4], ahi1[4], alo0[4], alo1[4];
            ldm_x4(ahi0, base + OFF_AHI + swz(wb + arow_lo, kc * 2 + asel));
            ldm_x4(ahi1, base + OFF_AHI + swz(wb + 16 + arow_lo, kc * 2 + asel));
            ldm_x4(alo0, base + OFF_ALO + swz(wb + arow_lo, kc * 2 + asel));
            ldm_x4(alo1, base + OFF_ALO + swz(wb + 16 + arow_lo, kc * 2 + asel));
            uint32_t bf[8][2];
#pragma unroll
            for (int p = 0; p < 4; p++) {
                uint32_t r[4];
                ldm_x4(r, base + OFF_BHI +
                           swz((2 * p + bnb_hi) * 8 + brow, kc * 2 + bchunk));
                bf[2 * p][0] = r[0]; bf[2 * p][1] = r[1];
                bf[2 * p + 1][0] = r[2]; bf[2 * p + 1][1] = r[3];
            }
#pragma unroll
            for (int nb = 0; nb < 8; nb++) {
                mma_f16(acc[0][nb], ahi0, bf[nb][0], bf[nb][1]);
                mma_f16(acc[1][nb], ahi1, bf[nb][0], bf[nb][1]);
                mma_f16(acc[0][nb], alo0, bf[nb][0], bf[nb][1]);
                mma_f16(acc[1][nb], alo1, bf[nb][0], bf[nb][1]);
            }
        }

        // ---- epilogue: +b2, LN2 (shfl), ReLU, dot W3 -----------------------
        int c4 = l & 3;
        float dd[4];
#pragma unroll
        for (int mf = 0; mf < 2; mf++) {
            float su0 = 0, qu0 = 0, su1 = 0, qu1 = 0;
#pragma unroll
            for (int nb = 0; nb < 8; nb++) {
                float4 e0 = __ldg(g_epi + nb * 8 + 2 * c4);
                float4 e1 = __ldg(g_epi + nb * 8 + 2 * c4 + 1);
                float a0 = acc[mf][nb][0] + e0.w;
                float a1 = acc[mf][nb][1] + e1.w;
                float a2 = acc[mf][nb][2] + e0.w;
                float a3 = acc[mf][nb][3] + e1.w;
                acc[mf][nb][0] = a0; acc[mf][nb][1] = a1;
                acc[mf][nb][2] = a2; acc[mf][nb][3] = a3;
                su0 += a0 + a1; qu0 = fmaf(a0, a0, fmaf(a1, a1, qu0));
                su1 += a2 + a3; qu1 = fmaf(a2, a2, fmaf(a3, a3, qu1));
            }
            su0 += __shfl_xor_sync(0xffffffffu, su0, 1);
            su0 += __shfl_xor_sync(0xffffffffu, su0, 2);
            qu0 += __shfl_xor_sync(0xffffffffu, qu0, 1);
            qu0 += __shfl_xor_sync(0xffffffffu, qu0, 2);
            su1 += __shfl_xor_sync(0xffffffffu, su1, 1);
            su1 += __shfl_xor_sync(0xffffffffu, su1, 2);
            qu1 += __shfl_xor_sync(0xffffffffu, qu1, 1);
            qu1 += __shfl_xor_sync(0xffffffffu, qu1, 2);

            float m0 = su0 * (1.f / 64.f);
            float v0 = qu0 * (1.f / 64.f) - m0 * m0;
            float rs0 = rsqrtf(v0 + 1e-5f), nm0 = -m0 * rs0;
            float m1 = su1 * (1.f / 64.f);
            float v1 = qu1 * (1.f / 64.f) - m1 * m1;
            float rs1 = rsqrtf(v1 + 1e-5f), nm1 = -m1 * rs1;

            float w0 = 0, w1 = 0;
#pragma unroll
            for (int nb = 0; nb < 8; nb++) {
                float4 e0 = __ldg(g_epi + nb * 8 + 2 * c4);
                float4 e1 = __ldg(g_epi + nb * 8 + 2 * c4 + 1);
                float y;
                y = fmaxf(fmaf(fmaf(acc[mf][nb][0], rs0, nm0), e0.x, e0.y), 0.f);
                w0 = fmaf(y, e0.z, w0);
                y = fmaxf(fmaf(fmaf(acc[mf][nb][1], rs0, nm0), e1.x, e1.y), 0.f);
                w0 = fmaf(y, e1.z, w0);
                y = fmaxf(fmaf(fmaf(acc[mf][nb][2], rs1, nm1), e0.x, e0.y), 0.f);
                w1 = fmaf(y, e0.z, w1);
                y = fmaxf(fmaf(fmaf(acc[mf][nb][3], rs1, nm1), e1.x, e1.y), 0.f);
                w1 = fmaf(y, e1.z, w1);
            }
            w0 += __shfl_xor_sync(0xffffffffu, w0, 1);
            w0 += __shfl_xor_sync(0xffffffffu, w0, 2);
            w1 += __shfl_xor_sync(0xffffffffu, w1, 1);
            w1 += __shfl_xor_sync(0xffffffffu, w1, 2);
            dd[mf * 2 + 0] = w0;
            dd[mf * 2 + 1] = w1;
        }

        // gather so lane l holds row wb+l -> coalesced mask load + store
        int src = (l & 7) * 4;
        float a0 = __shfl_sync(0xffffffffu, dd[0], src);
        float a1 = __shfl_sync(0xffffffffu, dd[1], src);
        float a2 = __shfl_sync(0xffffffffu, dd[2], src);
        float a3 = __shfl_sync(0xffffffffu, dd[3], src);
        float dv = (l < 8) ? a0 : (l < 16) ? a1 : (l < 24) ? a2 : a3;
        int jj = jbase + wb + l;
        int p = (i << 10) + jj;
        float sc = (dv + b3) * __ldg(mask + p);
        out[p] = (jj == i) ? 0.f : sc;

        __syncwarp();   // lanes rejoin before next tile's STS to the warp slice
    }
}

// ---------------- launch ----------------------------------------------------
extern "C" void kernel_launch(void* const* d_in, const int* in_sizes, int n_in,
                              void* d_out, int out_size) {
    const float* emb  = (const float*)d_in[0];
    const float* mask = (const float*)d_in[1];
    const float* W1   = (const float*)d_in[2];
    const float* b1   = (const float*)d_in[3];
    const float* g1   = (const float*)d_in[4];
    const float* be1  = (const float*)d_in[5];
    const float* W2   = (const float*)d_in[6];
    const float* b2   = (const float*)d_in[7];
    const float* g2   = (const float*)d_in[8];
    const float* be2  = (const float*)d_in[9];
    const float* W3   = (const float*)d_in[10];
    const float* b3   = (const float*)d_in[11];
    float* out = (float*)d_out;

    cudaFuncSetAttribute(pair_mlp_kernel,
                         cudaFuncAttributeMaxDynamicSharedMemorySize, SMEM_BYTES);

    precompute_all<<<NN + 64 + 1, 64>>>(emb, W1, b1, W2, g1, be1, g2, be2, W3, b2);
    pair_mlp_kernel<<<GRID_MAIN, 128, SMEM_BYTES>>>(mask, b3, out);
}

// round 5
// speedup vs baseline: 1.8086x; 1.5255x over previous
#include <cuda_runtime.h>
#include <cuda_fp16.h>
#include <cstdint>

// ============================================================================
// GraphConstructionActorHead — all N*N pair scores via factored 3-layer MLP.
//   pre: A[i]=emb_i@W1[:64]+b1 (row-major), B[j]=emb_j@W1[64:] stored in a
//     TRANSPOSED column-tile layout g_Bt[jb][quad][row] so the main kernel's
//     per-pair row reads are fully coalesced; per-node (sum,sumsq) stats;
//     W2^T fp16 swizzled; packed LN/epilogue consts.
//   main: tile = 128 pairs (one i, 128 j). Warp owns 32 rows end-to-end.
//     LN1 (stats via precomputed node stats + A·B dot) -> fp16 hi/lo split ->
//     warp-private smem -> ldmatrix -> 2-pass fp16 mma.sync (hiA+loA vs hiB;
//     b2 folded into accumulator init) -> LN2 + W3 dot on fragments (shfl,
//     single const-load pass) -> coalesced store.
// ============================================================================

#define NN 1024
#define NUM_TILES 8192
#define GRID_MAIN 608              // 4 CTAs/SM * 152 SMs, single wave
#define SMEM_BYTES 41984

// ---------------- device scratch --------------------------------------------
__device__ float g_A[NN * 64];
__device__ float g_Bt[NN * 64];             // [jb][16 quads][128 rows][4]
__device__ float2 g_stA[NN];                // (sum, sumsq) of A row
__device__ float2 g_stB[NN];
__device__ __half g_w2hi[64 * 64];          // [n][k] rows of 128B, XOR-swizzled
__device__ float4 g_gb1[32];                // (g1[2t],be1[2t],g1[2t+1],be1[2t+1])
__device__ float4 g_epi[64];                // per col: (g2, be2, W3, b2)

// ---------------- PTX helpers (family-common only) --------------------------
__device__ __forceinline__ uint32_t smem_to_u32(const void* p) {
    uint32_t a;
    asm("{ .reg .u64 t; cvta.to.shared.u64 t, %1; cvt.u32.u64 %0, t; }"
        : "=r"(a) : "l"(p));
    return a;
}
__device__ __forceinline__ void ldm_x4(uint32_t* r, uint32_t addr) {
    asm volatile("ldmatrix.sync.aligned.m8n8.x4.shared.b16 {%0,%1,%2,%3}, [%4];"
                 : "=r"(r[0]), "=r"(r[1]), "=r"(r[2]), "=r"(r[3]) : "r"(addr));
}
__device__ __forceinline__ void mma_f16(float* c, const uint32_t* a,
                                        uint32_t b0, uint32_t b1) {
    asm volatile(
        "mma.sync.aligned.m16n8k16.row.col.f32.f16.f16.f32 "
        "{%0,%1,%2,%3}, {%4,%5,%6,%7}, {%8,%9}, {%0,%1,%2,%3};"
        : "+f"(c[0]), "+f"(c[1]), "+f"(c[2]), "+f"(c[3])
        : "r"(a[0]), "r"(a[1]), "r"(a[2]), "r"(a[3]), "r"(b0), "r"(b1));
}
// swizzled byte offset within a [rows][128B] tile
__device__ __forceinline__ int swz(int row, int chunk) {
    return row * 128 + ((chunk ^ (row & 7)) << 4);
}

// ---------------- merged precompute (1 launch, 130 blocks x 512) ------------
// blocks 0..127: 8 nodes each -> A rows, Bt transposed tiles, stats
// block 128: W2 fp16 swizzle; block 129: packed consts
__global__ void precompute_all(const float* __restrict__ emb,
                               const float* __restrict__ W1,
                               const float* __restrict__ b1,
                               const float* __restrict__ W2,
                               const float* __restrict__ g1, const float* __restrict__ be1,
                               const float* __restrict__ g2, const float* __restrict__ be2,
                               const float* __restrict__ W3, const float* __restrict__ b2) {
    int bid = blockIdx.x;
    int tid = threadIdx.x;
    if (bid < 128) {
        __shared__ float e[8][64];
        __shared__ float part[8][2][4];
        int g = tid >> 6, h = tid & 63;
        int n = bid * 8 + g;
        e[g][h] = emb[n * 64 + h];
        __syncthreads();
        float a0 = b1[h], a1 = 0.f, c0 = 0.f, c1 = 0.f;
#pragma unroll
        for (int d = 0; d < 64; d += 2) {
            float e0 = e[g][d], e1 = e[g][d + 1];
            a0 = fmaf(e0, __ldg(W1 + d * 64 + h), a0);
            a1 = fmaf(e1, __ldg(W1 + (d + 1) * 64 + h), a1);
            c0 = fmaf(e0, __ldg(W1 + (64 + d) * 64 + h), c0);
            c1 = fmaf(e1, __ldg(W1 + (65 + d) * 64 + h), c1);
        }
        float a = a0 + a1, b = c0 + c1;
        g_A[n * 64 + h] = a;
        // transposed tile: [jb=n>>7][quad=h>>2][row=n&127][elem=h&3]
        g_Bt[(((n >> 7) * 16 + (h >> 2)) * 128 + (n & 127)) * 4 + (h & 3)] = b;
        float sa = a, qa = a * a, sb = b, qb = b * b;
#pragma unroll
        for (int o = 16; o > 0; o >>= 1) {
            sa += __shfl_xor_sync(0xffffffffu, sa, o);
            qa += __shfl_xor_sync(0xffffffffu, qa, o);
            sb += __shfl_xor_sync(0xffffffffu, sb, o);
            qb += __shfl_xor_sync(0xffffffffu, qb, o);
        }
        int w = (tid >> 5) & 1;
        if ((tid & 31) == 0) {
            part[g][w][0] = sa; part[g][w][1] = qa;
            part[g][w][2] = sb; part[g][w][3] = qb;
        }
        __syncthreads();
        if (tid < 8) {
            int nn = bid * 8 + tid;
            g_stA[nn] = make_float2(part[tid][0][0] + part[tid][1][0],
                                    part[tid][0][1] + part[tid][1][1]);
            g_stB[nn] = make_float2(part[tid][0][2] + part[tid][1][2],
                                    part[tid][0][3] + part[tid][1][3]);
        }
    } else if (bid == 128) {
#pragma unroll
        for (int u = 0; u < 8; u++) {
            int idx = tid + 512 * u;               // 0..4095
            int k = idx >> 6, n = idx & 63;
            float v = W2[k * 64 + n];              // B[n][k] = W2[k][n]
            int byte = swz(n, k >> 3) + (k & 7) * 2;
            g_w2hi[byte >> 1] = __float2half_rn(v);
        }
    } else {
        if (tid < 32) g_gb1[tid] = make_float4(g1[2 * tid], be1[2 * tid],
                                               g1[2 * tid + 1], be1[2 * tid + 1]);
        if (tid < 64) g_epi[tid] = make_float4(g2[tid], be2[tid], W3[tid], b2[tid]);
    }
}

// ---------------- main fused pair-MLP kernel --------------------------------
__global__ void __launch_bounds__(128, 4) pair_mlp_kernel(
    const float* __restrict__ mask, const float* __restrict__ b3p,
    float* __restrict__ out) {
    extern __shared__ char smem_raw[];
    uint32_t smem_u = smem_to_u32(smem_raw);
    uint32_t base = (smem_u + 1023) & ~1023u;
    char* basep = smem_raw + (base - smem_u);

    const uint32_t OFF_AHI = 0;        // h1 hi [128 rows x 128B] 16 KB
    const uint32_t OFF_ALO = 16384;    // h1 lo                   16 KB
    const uint32_t OFF_BHI = 32768;    // W2^T hi fp16 [64 x 128B] 8 KB

    int tid = threadIdx.x;
    int l = tid & 31;
    int wb = (tid >> 5) << 5;          // warp's 32-row slice base

    // copy pre-swizzled W2-hi into smem
    {
        uint4* ph = (uint4*)(basep + OFF_BHI);
        const uint4* shi = (const uint4*)g_w2hi;
#pragma unroll
        for (int t = 0; t < 4; t++) ph[tid + 128 * t] = __ldg(shi + tid + 128 * t);
    }
    __syncthreads();

    float b3 = __ldg(b3p);
    int arow_lo = ((l >> 3) & 1) * 8 + (l & 7);
    int asel = l >> 4;
    int brow = (l & 7);
    int bnb_hi = (l >> 4) & 1;
    int bchunk = (l >> 3) & 1;
    int c4 = l & 3;

    // b2 values folded into accumulator init (cols nb*8+2*c4, +1)
    float2 b2i[8];
#pragma unroll
    for (int nb = 0; nb < 8; nb++) {
        b2i[nb].x = __ldg(&g_epi[nb * 8 + 2 * c4].w);
        b2i[nb].y = __ldg(&g_epi[nb * 8 + 2 * c4 + 1].w);
    }

    // chunked schedule: consecutive tiles share jbase -> Bt block L1-resident
    int t0 = (int)(((long long)blockIdx.x * NUM_TILES) / GRID_MAIN);
    int t1 = (int)(((long long)(blockIdx.x + 1) * NUM_TILES) / GRID_MAIN);

    for (int T = t0; T < t1; T++) {
        int i = T & 1023;
        int jbase = (T >> 10) << 7;
        int j = jbase + tid;

        // ---- layer 1: x = A[i]+B[j]; LN stats via node stats + dot ---------
        float x[64];
        float d0 = 0, d1 = 0, d2 = 0, d3 = 0;
        {
            const float4* Ar = (const float4*)(g_A + i * 64);
            const float4* Br = (const float4*)g_Bt + (size_t)(T >> 10) * 2048 + tid;
#pragma unroll
            for (int t = 0; t < 16; t++) {
                float4 a = __ldg(Ar + t);
                float4 b = __ldg(Br + t * 128);    // coalesced: lane = row
                x[4 * t + 0] = a.x + b.x; x[4 * t + 1] = a.y + b.y;
                x[4 * t + 2] = a.z + b.z; x[4 * t + 3] = a.w + b.w;
                d0 = fmaf(a.x, b.x, d0); d1 = fmaf(a.y, b.y, d1);
                d2 = fmaf(a.z, b.z, d2); d3 = fmaf(a.w, b.w, d3);
            }
        }
        float2 stA = __ldg(g_stA + i);
        float2 stB = __ldg(g_stB + j);
        float dot = (d0 + d1) + (d2 + d3);
        float m  = (stA.x + stB.x) * (1.f / 64.f);
        float v  = (stA.y + stB.y + 2.f * dot) * (1.f / 64.f) - m * m;
        float rs = rsqrtf(v + 1e-5f);
        float nm = -m * rs;

        // LN1+ReLU, fp16 hi/lo split, write warp-private smem rows
#pragma unroll
        for (int c = 0; c < 8; c++) {
            float h[8];
#pragma unroll
            for (int u = 0; u < 4; u++) {
                int k = 8 * c + 2 * u;
                float4 gb = __ldg(g_gb1 + (k >> 1));
                float u0 = fmaf(x[k], rs, nm);
                float u1 = fmaf(x[k + 1], rs, nm);
                h[2 * u]     = fmaxf(fmaf(u0, gb.x, gb.y), 0.f);
                h[2 * u + 1] = fmaxf(fmaf(u1, gb.z, gb.w), 0.f);
            }
            uint32_t hiw[4], low[4];
#pragma unroll
            for (int u = 0; u < 4; u++) {
                __half2 hv = __floats2half2_rn(h[2 * u], h[2 * u + 1]);
                float2 hf = __half22float2(hv);
                __half2 lv = __floats2half2_rn(h[2 * u] - hf.x, h[2 * u + 1] - hf.y);
                hiw[u] = *(uint32_t*)&hv;
                low[u] = *(uint32_t*)&lv;
            }
            int off = swz(tid, c);
            *(uint4*)(basep + OFF_AHI + off) = make_uint4(hiw[0], hiw[1], hiw[2], hiw[3]);
            *(uint4*)(basep + OFF_ALO + off) = make_uint4(low[0], low[1], low[2], low[3]);
        }
        __syncwarp();   // warp-private rows: only intra-warp visibility needed

        // ---- layer 2 GEMM: 2-pass fp16, acc init = b2 ----------------------
        float acc[2][8][4];
#pragma unroll
        for (int nb = 0; nb < 8; nb++) {
            acc[0][nb][0] = b2i[nb].x; acc[0][nb][1] = b2i[nb].y;
            acc[0][nb][2] = b2i[nb].x; acc[0][nb][3] = b2i[nb].y;
            acc[1][nb][0] = b2i[nb].x; acc[1][nb][1] = b2i[nb].y;
            acc[1][nb][2] = b2i[nb].x; acc[1][nb][3] = b2i[nb].y;
        }
#pragma unroll
        for (int kc = 0; kc < 4; kc++) {
            uint32_t ahi0[4], ahi1[4], alo0[4], alo1[4];
            ldm_x4(ahi0, base + OFF_AHI + swz(wb + arow_lo, kc * 2 + asel));
            ldm_x4(ahi1, base + OFF_AHI + swz(wb + 16 + arow_lo, kc * 2 + asel));
            ldm_x4(alo0, base + OFF_ALO + swz(wb + arow_lo, kc * 2 + asel));
            ldm_x4(alo1, base + OFF_ALO + swz(wb + 16 + arow_lo, kc * 2 + asel));
#pragma unroll
            for (int p = 0; p < 4; p++) {
                uint32_t r[4];
                ldm_x4(r, base + OFF_BHI +
                           swz((2 * p + bnb_hi) * 8 + brow, kc * 2 + bchunk));
                mma_f16(acc[0][2 * p],     ahi0, r[0], r[1]);
                mma_f16(acc[1][2 * p],     ahi1, r[0], r[1]);
                mma_f16(acc[0][2 * p],     alo0, r[0], r[1]);
                mma_f16(acc[1][2 * p],     alo1, r[0], r[1]);
                mma_f16(acc[0][2 * p + 1], ahi0, r[2], r[3]);
                mma_f16(acc[1][2 * p + 1], ahi1, r[2], r[3]);
                mma_f16(acc[0][2 * p + 1], alo0, r[2], r[3]);
                mma_f16(acc[1][2 * p + 1], alo1, r[2], r[3]);
            }
        }

        // ---- epilogue: LN2 stats (b2 already in acc), single const pass ----
        float rs0[2], nm0[2], rs1[2], nm1[2];
#pragma unroll
        for (int mf = 0; mf < 2; mf++) {
            float su0 = 0, qu0 = 0, su1 = 0, qu1 = 0;
#pragma unroll
            for (int nb = 0; nb < 8; nb++) {
                float a0 = acc[mf][nb][0], a1 = acc[mf][nb][1];
                float a2 = acc[mf][nb][2], a3 = acc[mf][nb][3];
                su0 += a0 + a1; qu0 = fmaf(a0, a0, fmaf(a1, a1, qu0));
                su1 += a2 + a3; qu1 = fmaf(a2, a2, fmaf(a3, a3, qu1));
            }
            su0 += __shfl_xor_sync(0xffffffffu, su0, 1);
            su0 += __shfl_xor_sync(0xffffffffu, su0, 2);
            qu0 += __shfl_xor_sync(0xffffffffu, qu0, 1);
            qu0 += __shfl_xor_sync(0xffffffffu, qu0, 2);
            su1 += __shfl_xor_sync(0xffffffffu, su1, 1);
            su1 += __shfl_xor_sync(0xffffffffu, su1, 2);
            qu1 += __shfl_xor_sync(0xffffffffu, qu1, 1);
            qu1 += __shfl_xor_sync(0xffffffffu, qu1, 2);
            float m0 = su0 * (1.f / 64.f);
            float v0 = qu0 * (1.f / 64.f) - m0 * m0;
            rs0[mf] = rsqrtf(v0 + 1e-5f); nm0[mf] = -m0 * rs0[mf];
            float m1 = su1 * (1.f / 64.f);
            float v1 = qu1 * (1.f / 64.f) - m1 * m1;
            rs1[mf] = rsqrtf(v1 + 1e-5f); nm1[mf] = -m1 * rs1[mf];
        }

        float w00 = 0, w01 = 0, w10 = 0, w11 = 0;   // [mf][row-half]
#pragma unroll
        for (int nb = 0; nb < 8; nb++) {
            float4 e0 = __ldg(g_epi + nb * 8 + 2 * c4);
            float4 e1 = __ldg(g_epi + nb * 8 + 2 * c4 + 1);
            float y;
            y = fmaxf(fmaf(fmaf(acc[0][nb][0], rs0[0], nm0[0]), e0.x, e0.y), 0.f);
            w00 = fmaf(y, e0.z, w00);
            y = fmaxf(fmaf(fmaf(acc[0][nb][1], rs0[0], nm0[0]), e1.x, e1.y), 0.f);
            w00 = fmaf(y, e1.z, w00);
            y = fmaxf(fmaf(fmaf(acc[0][nb][2], rs1[0], nm1[0]), e0.x, e0.y), 0.f);
            w01 = fmaf(y, e0.z, w01);
            y = fmaxf(fmaf(fmaf(acc[0][nb][3], rs1[0], nm1[0]), e1.x, e1.y), 0.f);
            w01 = fmaf(y, e1.z, w01);
            y = fmaxf(fmaf(fmaf(acc[1][nb][0], rs0[1], nm0[1]), e0.x, e0.y), 0.f);
            w10 = fmaf(y, e0.z, w10);
            y = fmaxf(fmaf(fmaf(acc[1][nb][1], rs0[1], nm0[1]), e1.x, e1.y), 0.f);
            w10 = fmaf(y, e1.z, w10);
            y = fmaxf(fmaf(fmaf(acc[1][nb][2], rs1[1], nm1[1]), e0.x, e0.y), 0.f);
            w11 = fmaf(y, e0.z, w11);
            y = fmaxf(fmaf(fmaf(acc[1][nb][3], rs1[1], nm1[1]), e1.x, e1.y), 0.f);
            w11 = fmaf(y, e1.z, w11);
        }
        w00 += __shfl_xor_sync(0xffffffffu, w00, 1);
        w00 += __shfl_xor_sync(0xffffffffu, w00, 2);
        w01 += __shfl_xor_sync(0xffffffffu, w01, 1);
        w01 += __shfl_xor_sync(0xffffffffu, w01, 2);
        w10 += __shfl_xor_sync(0xffffffffu, w10, 1);
        w10 += __shfl_xor_sync(0xffffffffu, w10, 2);
        w11 += __shfl_xor_sync(0xffffffffu, w11, 1);
        w11 += __shfl_xor_sync(0xffffffffu, w11, 2);

        // gather so lane l holds row wb+l -> coalesced mask load + store
        int src = (l & 7) * 4;
        float a0 = __shfl_sync(0xffffffffu, w00, src);
        float a1 = __shfl_sync(0xffffffffu, w01, src);
        float a2 = __shfl_sync(0xffffffffu, w10, src);
        float a3 = __shfl_sync(0xffffffffu, w11, src);
        float dv = (l < 8) ? a0 : (l < 16) ? a1 : (l < 24) ? a2 : a3;
        int jj = jbase + wb + l;
        int p = (i << 10) + jj;
        float sc = (dv + b3) * __ldg(mask + p);
        out[p] = (jj == i) ? 0.f : sc;

        __syncwarp();   // lanes rejoin before next tile's STS to the warp slice
    }
}

// ---------------- launch ----------------------------------------------------
extern "C" void kernel_launch(void* const* d_in, const int* in_sizes, int n_in,
                              void* d_out, int out_size) {
    const float* emb  = (const float*)d_in[0];
    const float* mask = (const float*)d_in[1];
    const float* W1   = (const float*)d_in[2];
    const float* b1   = (const float*)d_in[3];
    const float* g1   = (const float*)d_in[4];
    const float* be1  = (const float*)d_in[5];
    const float* W2   = (const float*)d_in[6];
    const float* b2   = (const float*)d_in[7];
    const float* g2   = (const float*)d_in[8];
    const float* be2  = (const float*)d_in[9];
    const float* W3   = (const float*)d_in[10];
    const float* b3   = (const float*)d_in[11];
    float* out = (float*)d_out;

    cudaFuncSetAttribute(pair_mlp_kernel,
                         cudaFuncAttributeMaxDynamicSharedMemorySize, SMEM_BYTES);

    precompute_all<<<130, 512>>>(emb, W1, b1, W2, g1, be1, g2, be2, W3, b2);
    pair_mlp_kernel<<<GRID_MAIN, 128, SMEM_BYTES>>>(mask, b3, out);
}

// round 7
// speedup vs baseline: 1.9193x; 1.0612x over previous
#include <cuda_runtime.h>
#include <cuda_fp16.h>
#include <cstdint>

// ============================================================================
// GraphConstructionActorHead — all N*N pair scores via factored 3-layer MLP.
//   pre: A[i]=emb_i@W1[:64]+b1 (row-major), B[j]=emb_j@W1[64:] in transposed
//     column-tile layout (coalesced per-pair reads); per-node (sum,sumsq);
//     W2^T fp16 swizzled; packed LN/epilogue consts -> __constant__.
//   main: tile = 128 pairs (one i, 128 j). Warp owns 32 rows end-to-end.
//     LN1 (precomputed stats + A·B dot) -> fp16 -> warp-private smem ->
//     ldmatrix -> SINGLE-pass fp16 mma.sync (W2 fragments register-resident;
//     calibrated residual ~5e-4 < 1e-3) -> LN2 + W3 dot on fragments (shfl,
//     consts from constant cache) -> coalesced store.
//   3 CTAs/SM (regs<=170), single wave, chunked schedule.
// ============================================================================

#define NN 1024
#define NUM_TILES 8192
#define GRID_MAIN 456              // 3 CTAs/SM * 152 SMs, single wave
#define SMEM_BYTES 25600

// ---------------- device scratch --------------------------------------------
__device__ float g_A[NN * 64];
__device__ float g_Bt[NN * 64];             // [jb][16 quads][128 rows][4]
__device__ float2 g_stA[NN];
__device__ float2 g_stB[NN];
__device__ __half g_w2hi[64 * 64];          // [n][k] rows of 128B, XOR-swizzled
__device__ float4 g_gb1d[32];               // staging for constant copies
__device__ float4 g_epid[64];

__constant__ float4 c_gb1[32];              // (g1[2t],be1[2t],g1[2t+1],be1[2t+1])
__constant__ float4 c_epi[64];              // per col: (g2, be2, W3, b2)

// ---------------- PTX helpers (family-common only) --------------------------
__device__ __forceinline__ uint32_t smem_to_u32(const void* p) {
    uint32_t a;
    asm("{ .reg .u64 t; cvta.to.shared.u64 t, %1; cvt.u32.u64 %0, t; }"
        : "=r"(a) : "l"(p));
    return a;
}
__device__ __forceinline__ void ldm_x4(uint32_t* r, uint32_t addr) {
    asm volatile("ldmatrix.sync.aligned.m8n8.x4.shared.b16 {%0,%1,%2,%3}, [%4];"
                 : "=r"(r[0]), "=r"(r[1]), "=r"(r[2]), "=r"(r[3]) : "r"(addr));
}
__device__ __forceinline__ void ldm_x2(uint32_t& r0, uint32_t& r1, uint32_t addr) {
    asm volatile("ldmatrix.sync.aligned.m8n8.x2.shared.b16 {%0,%1}, [%2];"
                 : "=r"(r0), "=r"(r1) : "r"(addr));
}
__device__ __forceinline__ void mma_f16(float* c, const uint32_t* a,
                                        uint32_t b0, uint32_t b1) {
    asm volatile(
        "mma.sync.aligned.m16n8k16.row.col.f32.f16.f16.f32 "
        "{%0,%1,%2,%3}, {%4,%5,%6,%7}, {%8,%9}, {%0,%1,%2,%3};"
        : "+f"(c[0]), "+f"(c[1]), "+f"(c[2]), "+f"(c[3])
        : "r"(a[0]), "r"(a[1]), "r"(a[2]), "r"(a[3]), "r"(b0), "r"(b1));
}
__device__ __forceinline__ int swz(int row, int chunk) {
    return row * 128 + ((chunk ^ (row & 7)) << 4);
}

// ---------------- merged precompute (1 launch, 130 blocks x 512) ------------
__global__ void precompute_all(const float* __restrict__ emb,
                               const float* __restrict__ W1,
                               const float* __restrict__ b1,
                               const float* __restrict__ W2,
                               const float* __restrict__ g1, const float* __restrict__ be1,
                               const float* __restrict__ g2, const float* __restrict__ be2,
                               const float* __restrict__ W3, const float* __restrict__ b2) {
    int bid = blockIdx.x;
    int tid = threadIdx.x;
    if (bid < 128) {
        __shared__ float e[8][64];
        __shared__ float part[8][2][4];
        int g = tid >> 6, h = tid & 63;
        int n = bid * 8 + g;
        e[g][h] = emb[n * 64 + h];
        __syncthreads();
        float a0 = b1[h], a1 = 0.f, c0 = 0.f, c1 = 0.f;
#pragma unroll
        for (int d = 0; d < 64; d += 2) {
            float e0 = e[g][d], e1 = e[g][d + 1];
            a0 = fmaf(e0, __ldg(W1 + d * 64 + h), a0);
            a1 = fmaf(e1, __ldg(W1 + (d + 1) * 64 + h), a1);
            c0 = fmaf(e0, __ldg(W1 + (64 + d) * 64 + h), c0);
            c1 = fmaf(e1, __ldg(W1 + (65 + d) * 64 + h), c1);
        }
        float a = a0 + a1, b = c0 + c1;
        g_A[n * 64 + h] = a;
        g_Bt[(((n >> 7) * 16 + (h >> 2)) * 128 + (n & 127)) * 4 + (h & 3)] = b;
        float sa = a, qa = a * a, sb = b, qb = b * b;
#pragma unroll
        for (int o = 16; o > 0; o >>= 1) {
            sa += __shfl_xor_sync(0xffffffffu, sa, o);
            qa += __shfl_xor_sync(0xffffffffu, qa, o);
            sb += __shfl_xor_sync(0xffffffffu, sb, o);
            qb += __shfl_xor_sync(0xffffffffu, qb, o);
        }
        int w = (tid >> 5) & 1;
        if ((tid & 31) == 0) {
            part[g][w][0] = sa; part[g][w][1] = qa;
            part[g][w][2] = sb; part[g][w][3] = qb;
        }
        __syncthreads();
        if (tid < 8) {
            int nn = bid * 8 + tid;
            g_stA[nn] = make_float2(part[tid][0][0] + part[tid][1][0],
                                    part[tid][0][1] + part[tid][1][1]);
            g_stB[nn] = make_float2(part[tid][0][2] + part[tid][1][2],
                                    part[tid][0][3] + part[tid][1][3]);
        }
    } else if (bid == 128) {
#pragma unroll
        for (int u = 0; u < 8; u++) {
            int idx = tid + 512 * u;               // 0..4095
            int k = idx >> 6, n = idx & 63;
            float v = W2[k * 64 + n];              // B[n][k] = W2[k][n]
            int byte = swz(n, k >> 3) + (k & 7) * 2;
            g_w2hi[byte >> 1] = __float2half_rn(v);
        }
    } else {
        if (tid < 32) g_gb1d[tid] = make_float4(g1[2 * tid], be1[2 * tid],
                                                g1[2 * tid + 1], be1[2 * tid + 1]);
        if (tid < 64) g_epid[tid] = make_float4(g2[tid], be2[tid], W3[tid], b2[tid]);
    }
}

// ---------------- main fused pair-MLP kernel --------------------------------
__global__ void __launch_bounds__(128, 3) pair_mlp_kernel(
    const float* __restrict__ mask, const float* __restrict__ b3p,
    float* __restrict__ out) {
    extern __shared__ char smem_raw[];
    uint32_t smem_u = smem_to_u32(smem_raw);
    uint32_t base = (smem_u + 1023) & ~1023u;
    char* basep = smem_raw + (base - smem_u);

    const uint32_t OFF_AHI = 0;        // h1 fp16 [128 rows x 128B] 16 KB
    const uint32_t OFF_BHI = 16384;    // W2^T fp16 [64 x 128B]      8 KB

    int tid = threadIdx.x;
    int l = tid & 31;
    int wb = (tid >> 5) << 5;          // warp's 32-row slice base

    // copy pre-swizzled W2-hi into smem (startup only)
    {
        uint4* ph = (uint4*)(basep + OFF_BHI);
        const uint4* shi = (const uint4*)g_w2hi;
#pragma unroll
        for (int t = 0; t < 4; t++) ph[tid + 128 * t] = __ldg(shi + tid + 128 * t);
    }
    __syncthreads();

    // W2 fragments register-resident for the whole kernel: bf[kc][nb][2]
    int bl = l & 15;
    int brow_lo = bl & 7, bsel = bl >> 3;
    uint32_t bf[4][8][2];
#pragma unroll
    for (int kc = 0; kc < 4; kc++)
#pragma unroll
        for (int nb = 0; nb < 8; nb++)
            ldm_x2(bf[kc][nb][0], bf[kc][nb][1],
                   base + OFF_BHI + swz(nb * 8 + brow_lo, kc * 2 + bsel));

    float b3 = __ldg(b3p);
    int arow_lo = ((l >> 3) & 1) * 8 + (l & 7);
    int asel = l >> 4;
    int c4 = l & 3;

    // chunked schedule: consecutive tiles share jbase -> Bt block L1-resident
    int t0 = (int)(((long long)blockIdx.x * NUM_TILES) / GRID_MAIN);
    int t1 = (int)(((long long)(blockIdx.x + 1) * NUM_TILES) / GRID_MAIN);

    for (int T = t0; T < t1; T++) {
        int i = T & 1023;
        int jbase = (T >> 10) << 7;
        int j = jbase + tid;

        // ---- layer 1: x = A[i]+B[j]; LN stats via node stats + dot ---------
        float x[64];
        float d0 = 0, d1 = 0, d2 = 0, d3 = 0;
        {
            const float4* Ar = (const float4*)(g_A + i * 64);
            const float4* Br = (const float4*)g_Bt + (size_t)(T >> 10) * 2048 + tid;
#pragma unroll
            for (int t = 0; t < 16; t++) {
                float4 a = __ldg(Ar + t);
                float4 b = __ldg(Br + t * 128);    // coalesced: lane = row
                x[4 * t + 0] = a.x + b.x; x[4 * t + 1] = a.y + b.y;
                x[4 * t + 2] = a.z + b.z; x[4 * t + 3] = a.w + b.w;
                d0 = fmaf(a.x, b.x, d0); d1 = fmaf(a.y, b.y, d1);
                d2 = fmaf(a.z, b.z, d2); d3 = fmaf(a.w, b.w, d3);
            }
        }
        float2 stA = __ldg(g_stA + i);
        float2 stB = __ldg(g_stB + j);
        float dot = (d0 + d1) + (d2 + d3);
        float m  = (stA.x + stB.x) * (1.f / 64.f);
        float v  = (stA.y + stB.y + 2.f * dot) * (1.f / 64.f) - m * m;
        float rs = rsqrtf(v + 1e-5f);
        float nm = -m * rs;

        // LN1+ReLU, fp16, write warp-private smem rows
#pragma unroll
        for (int c = 0; c < 8; c++) {
            uint32_t hiw[4];
#pragma unroll
            for (int u = 0; u < 4; u++) {
                int k = 8 * c + 2 * u;
                float4 gb = c_gb1[k >> 1];         // uniform -> const port
                float u0 = fmaf(x[k], rs, nm);
                float u1 = fmaf(x[k + 1], rs, nm);
                float h0 = fmaxf(fmaf(u0, gb.x, gb.y), 0.f);
                float h1 = fmaxf(fmaf(u1, gb.z, gb.w), 0.f);
                __half2 hv = __floats2half2_rn(h0, h1);
                hiw[u] = *(uint32_t*)&hv;
            }
            int off = swz(tid, c);
            *(uint4*)(basep + OFF_AHI + off) = make_uint4(hiw[0], hiw[1], hiw[2], hiw[3]);
        }
        __syncwarp();   // warp-private rows: only intra-warp visibility needed

        // ---- layer 2 GEMM: single-pass fp16, resident W2 fragments ---------
        float acc[2][8][4] = {};
#pragma unroll
        for (int kc = 0; kc < 4; kc++) {
            uint32_t ahi0[4], ahi1[4];
            ldm_x4(ahi0, base + OFF_AHI + swz(wb + arow_lo, kc * 2 + asel));
            ldm_x4(ahi1, base + OFF_AHI + swz(wb + 16 + arow_lo, kc * 2 + asel));
#pragma unroll
            for (int nb = 0; nb < 8; nb++) {
                mma_f16(acc[0][nb], ahi0, bf[kc][nb][0], bf[kc][nb][1]);
                mma_f16(acc[1][nb], ahi1, bf[kc][nb][0], bf[kc][nb][1]);
            }
        }

        // ---- epilogue: +b2, LN2 stats (shfl), ReLU, dot W3 -----------------
#pragma unroll
        for (int nb = 0; nb < 8; nb++) {
            float w0 = c_epi[nb * 8 + 2 * c4].w;
            float w1 = c_epi[nb * 8 + 2 * c4 + 1].w;
            acc[0][nb][0] += w0; acc[0][nb][1] += w1;
            acc[0][nb][2] += w0; acc[0][nb][3] += w1;
            acc[1][nb][0] += w0; acc[1][nb][1] += w1;
            acc[1][nb][2] += w0; acc[1][nb][3] += w1;
        }
        float rs0[2], nm0[2], rs1[2], nm1[2];
#pragma unroll
        for (int mf = 0; mf < 2; mf++) {
            float su0 = 0, qu0 = 0, su1 = 0, qu1 = 0;
#pragma unroll
            for (int nb = 0; nb < 8; nb++) {
                float a0 = acc[mf][nb][0], a1 = acc[mf][nb][1];
                float a2 = acc[mf][nb][2], a3 = acc[mf][nb][3];
                su0 += a0 + a1; qu0 = fmaf(a0, a0, fmaf(a1, a1, qu0));
                su1 += a2 + a3; qu1 = fmaf(a2, a2, fmaf(a3, a3, qu1));
            }
            su0 += __shfl_xor_sync(0xffffffffu, su0, 1);
            su0 += __shfl_xor_sync(0xffffffffu, su0, 2);
            qu0 += __shfl_xor_sync(0xffffffffu, qu0, 1);
            qu0 += __shfl_xor_sync(0xffffffffu, qu0, 2);
            su1 += __shfl_xor_sync(0xffffffffu, su1, 1);
            su1 += __shfl_xor_sync(0xffffffffu, su1, 2);
            qu1 += __shfl_xor_sync(0xffffffffu, qu1, 1);
            qu1 += __shfl_xor_sync(0xffffffffu, qu1, 2);
            float m0 = su0 * (1.f / 64.f);
            float v0 = qu0 * (1.f / 64.f) - m0 * m0;
            rs0[mf] = rsqrtf(v0 + 1e-5f); nm0[mf] = -m0 * rs0[mf];
            float m1 = su1 * (1.f / 64.f);
            float v1 = qu1 * (1.f / 64.f) - m1 * m1;
            rs1[mf] = rsqrtf(v1 + 1e-5f); nm1[mf] = -m1 * rs1[mf];
        }

        float w00 = 0, w01 = 0, w10 = 0, w11 = 0;
#pragma unroll
        for (int nb = 0; nb < 8; nb++) {
            float4 e0 = c_epi[nb * 8 + 2 * c4];
            float4 e1 = c_epi[nb * 8 + 2 * c4 + 1];
            float y;
            y = fmaxf(fmaf(fmaf(acc[0][nb][0], rs0[0], nm0[0]), e0.x, e0.y), 0.f);
            w00 = fmaf(y, e0.z, w00);
            y = fmaxf(fmaf(fmaf(acc[0][nb][1], rs0[0], nm0[0]), e1.x, e1.y), 0.f);
            w00 = fmaf(y, e1.z, w00);
            y = fmaxf(fmaf(fmaf(acc[0][nb][2], rs1[0], nm1[0]), e0.x, e0.y), 0.f);
            w01 = fmaf(y, e0.z, w01);
            y = fmaxf(fmaf(fmaf(acc[0][nb][3], rs1[0], nm1[0]), e1.x, e1.y), 0.f);
            w01 = fmaf(y, e1.z, w01);
            y = fmaxf(fmaf(fmaf(acc[1][nb][0], rs0[1], nm0[1]), e0.x, e0.y), 0.f);
            w10 = fmaf(y, e0.z, w10);
            y = fmaxf(fmaf(fmaf(acc[1][nb][1], rs0[1], nm0[1]), e1.x, e1.y), 0.f);
            w10 = fmaf(y, e1.z, w10);
            y = fmaxf(fmaf(fmaf(acc[1][nb][2], rs1[1], nm1[1]), e0.x, e0.y), 0.f);
            w11 = fmaf(y, e0.z, w11);
            y = fmaxf(fmaf(fmaf(acc[1][nb][3], rs1[1], nm1[1]), e1.x, e1.y), 0.f);
            w11 = fmaf(y, e1.z, w11);
        }
        w00 += __shfl_xor_sync(0xffffffffu, w00, 1);
        w00 += __shfl_xor_sync(0xffffffffu, w00, 2);
        w01 += __shfl_xor_sync(0xffffffffu, w01, 1);
        w01 += __shfl_xor_sync(0xffffffffu, w01, 2);
        w10 += __shfl_xor_sync(0xffffffffu, w10, 1);
        w10 += __shfl_xor_sync(0xffffffffu, w10, 2);
        w11 += __shfl_xor_sync(0xffffffffu, w11, 1);
        w11 += __shfl_xor_sync(0xffffffffu, w11, 2);

        // gather so lane l holds row wb+l -> coalesced mask load + store
        int src = (l & 7) * 4;
        float a0 = __shfl_sync(0xffffffffu, w00, src);
        float a1 = __shfl_sync(0xffffffffu, w01, src);
        float a2 = __shfl_sync(0xffffffffu, w10, src);
        float a3 = __shfl_sync(0xffffffffu, w11, src);
        float dv = (l < 8) ? a0 : (l < 16) ? a1 : (l < 24) ? a2 : a3;
        int jj = jbase + wb + l;
        int p = (i << 10) + jj;
        float sc = (dv + b3) * __ldg(mask + p);
        out[p] = (jj == i) ? 0.f : sc;

        __syncwarp();   // lanes rejoin before next tile's STS to the warp slice
    }
}

// ---------------- launch ----------------------------------------------------
extern "C" void kernel_launch(void* const* d_in, const int* in_sizes, int n_in,
                              void* d_out, int out_size) {
    const float* emb  = (const float*)d_in[0];
    const float* mask = (const float*)d_in[1];
    const float* W1   = (const float*)d_in[2];
    const float* b1   = (const float*)d_in[3];
    const float* g1   = (const float*)d_in[4];
    const float* be1  = (const float*)d_in[5];
    const float* W2   = (const float*)d_in[6];
    const float* b2   = (const float*)d_in[7];
    const float* g2   = (const float*)d_in[8];
    const float* be2  = (const float*)d_in[9];
    const float* W3   = (const float*)d_in[10];
    const float* b3   = (const float*)d_in[11];
    float* out = (float*)d_out;

    cudaFuncSetAttribute(pair_mlp_kernel,
                         cudaFuncAttributeMaxDynamicSharedMemorySize, SMEM_BYTES);

    precompute_all<<<130, 512>>>(emb, W1, b1, W2, g1, be1, g2, be2, W3, b2);

    // stage packed consts into __constant__ (async D2D copies, capturable)
    void* pgb = nullptr; void* pep = nullptr;
    cudaGetSymbolAddress(&pgb, g_gb1d);
    cudaGetSymbolAddress(&pep, g_epid);
    cudaMemcpyToSymbolAsync(c_gb1, pgb, 32 * sizeof(float4), 0,
                            cudaMemcpyDeviceToDevice, 0);
    cudaMemcpyToSymbolAsync(c_epi, pep, 64 * sizeof(float4), 0,
                            cudaMemcpyDeviceToDevice, 0);

    pair_mlp_kernel<<<GRID_MAIN, 128, SMEM_BYTES>>>(mask, b3, out);
}